// round 5
// baseline (speedup 1.0000x reference)
#include <cuda_runtime.h>

// Row-wise cosine similarity * 0.5 over [B=16384, D=4096] fp32.
// v3: CTA processes 2 rows, software-pipelined. All loads per row are
// front-batched (8 x float4 per thread, like v1 which hit 88.1% DRAM);
// row1's loads issue while row0's shuffle-reduction runs, hiding the
// reduction bubble. One __syncthreads per 2 rows.

#define D_DIM 4096
#define THREADS 256
#define ROWS_PER_CTA 2
// Per row: 1024 float4 per input; per thread: 4 float4 per input.

__global__ __launch_bounds__(THREADS) void cosine_rows2_kernel(
    const float* __restrict__ x1,
    const float* __restrict__ x2,
    float* __restrict__ out)
{
    const int tid = threadIdx.x;
    const int row0 = blockIdx.x * ROWS_PER_CTA;
    const int row1 = row0 + 1;

    const float4* r1a = reinterpret_cast<const float4*>(x1 + (size_t)row0 * D_DIM);
    const float4* r2a = reinterpret_cast<const float4*>(x2 + (size_t)row0 * D_DIM);
    const float4* r1b = reinterpret_cast<const float4*>(x1 + (size_t)row1 * D_DIM);
    const float4* r2b = reinterpret_cast<const float4*>(x2 + (size_t)row1 * D_DIM);

    float d0 = 0.f, sx0 = 0.f, sy0 = 0.f;
    float d1 = 0.f, sx1 = 0.f, sy1 = 0.f;

    // ---- row0: batch 8 loads, then FMA ----
    {
        float4 a[4], b[4];
#pragma unroll
        for (int i = 0; i < 4; ++i) {
            a[i] = __ldcs(&r1a[tid + i * THREADS]);
            b[i] = __ldcs(&r2a[tid + i * THREADS]);
        }
#pragma unroll
        for (int i = 0; i < 4; ++i) {
            d0  = fmaf(a[i].x, b[i].x, d0);
            d0  = fmaf(a[i].y, b[i].y, d0);
            d0  = fmaf(a[i].z, b[i].z, d0);
            d0  = fmaf(a[i].w, b[i].w, d0);
            sx0 = fmaf(a[i].x, a[i].x, sx0);
            sx0 = fmaf(a[i].y, a[i].y, sx0);
            sx0 = fmaf(a[i].z, a[i].z, sx0);
            sx0 = fmaf(a[i].w, a[i].w, sx0);
            sy0 = fmaf(b[i].x, b[i].x, sy0);
            sy0 = fmaf(b[i].y, b[i].y, sy0);
            sy0 = fmaf(b[i].z, b[i].z, sy0);
            sy0 = fmaf(b[i].w, b[i].w, sy0);
        }
    }

    // ---- row1: issue 8 batched loads NOW (row0 regs are dead, reused);
    //      these fly while row0's shuffle chain below executes ----
    float4 c[4], e[4];
#pragma unroll
    for (int i = 0; i < 4; ++i) {
        c[i] = __ldcs(&r1b[tid + i * THREADS]);
        e[i] = __ldcs(&r2b[tid + i * THREADS]);
    }

    // ---- row0 warp-level reduce (covers row1 load latency) ----
#pragma unroll
    for (int off = 16; off > 0; off >>= 1) {
        d0  += __shfl_down_sync(0xFFFFFFFFu, d0,  off);
        sx0 += __shfl_down_sync(0xFFFFFFFFu, sx0, off);
        sy0 += __shfl_down_sync(0xFFFFFFFFu, sy0, off);
    }

    // ---- row1 FMA ----
#pragma unroll
    for (int i = 0; i < 4; ++i) {
        d1  = fmaf(c[i].x, e[i].x, d1);
        d1  = fmaf(c[i].y, e[i].y, d1);
        d1  = fmaf(c[i].z, e[i].z, d1);
        d1  = fmaf(c[i].w, e[i].w, d1);
        sx1 = fmaf(c[i].x, c[i].x, sx1);
        sx1 = fmaf(c[i].y, c[i].y, sx1);
        sx1 = fmaf(c[i].z, c[i].z, sx1);
        sx1 = fmaf(c[i].w, c[i].w, sx1);
        sy1 = fmaf(e[i].x, e[i].x, sy1);
        sy1 = fmaf(e[i].y, e[i].y, sy1);
        sy1 = fmaf(e[i].z, e[i].z, sy1);
        sy1 = fmaf(e[i].w, e[i].w, sy1);
    }

    // ---- row1 warp-level reduce ----
#pragma unroll
    for (int off = 16; off > 0; off >>= 1) {
        d1  += __shfl_down_sync(0xFFFFFFFFu, d1,  off);
        sx1 += __shfl_down_sync(0xFFFFFFFFu, sx1, off);
        sy1 += __shfl_down_sync(0xFFFFFFFFu, sy1, off);
    }

    // ---- single cross-warp stage for all 6 partials ----
    __shared__ float s[6][8];
    const int wid = tid >> 5;
    const int lid = tid & 31;
    if (lid == 0) {
        s[0][wid] = d0;  s[1][wid] = sx0;  s[2][wid] = sy0;
        s[3][wid] = d1;  s[4][wid] = sx1;  s[5][wid] = sy1;
    }
    __syncthreads();

    if (wid == 0) {
        float v0 = (lid < 8) ? s[0][lid] : 0.f;
        float v1 = (lid < 8) ? s[1][lid] : 0.f;
        float v2 = (lid < 8) ? s[2][lid] : 0.f;
        float v3 = (lid < 8) ? s[3][lid] : 0.f;
        float v4 = (lid < 8) ? s[4][lid] : 0.f;
        float v5 = (lid < 8) ? s[5][lid] : 0.f;
#pragma unroll
        for (int off = 4; off > 0; off >>= 1) {
            v0 += __shfl_down_sync(0xFFFFFFFFu, v0, off);
            v1 += __shfl_down_sync(0xFFFFFFFFu, v1, off);
            v2 += __shfl_down_sync(0xFFFFFFFFu, v2, off);
            v3 += __shfl_down_sync(0xFFFFFFFFu, v3, off);
            v4 += __shfl_down_sync(0xFFFFFFFFu, v4, off);
            v5 += __shfl_down_sync(0xFFFFFFFFu, v5, off);
        }
        if (lid == 0) {
            out[row0] = 0.5f * v0 * rsqrtf(v1 * v2);
            out[row1] = 0.5f * v3 * rsqrtf(v4 * v5);
        }
    }
}

extern "C" void kernel_launch(void* const* d_in, const int* in_sizes, int n_in,
                              void* d_out, int out_size)
{
    const float* x1 = (const float*)d_in[0];
    const float* x2 = (const float*)d_in[1];
    float* out = (float*)d_out;
    const int B = out_size;  // 16384 rows
    cosine_rows2_kernel<<<B / ROWS_PER_CTA, THREADS>>>(x1, x2, out);
}

// round 6
// speedup vs baseline: 1.0843x; 1.0843x over previous
#include <cuda_runtime.h>

// Row-wise cosine similarity * 0.5 over [B=16384, D=4096] fp32.
// v4: one CTA (128 threads) per row, 16-deep front-batched LDG.128 burst
// per thread (8 float4 from each input) -> MLP_p1=16 vs v1's 8.
// Default caching (no __ldcs - correlated with v2/v3 regressions).

#define D_DIM 4096
#define THREADS 128
// Per row: 1024 float4 per input; per thread: 8 float4 per input.

__global__ __launch_bounds__(THREADS) void cosine_rows_deep_kernel(
    const float* __restrict__ x1,
    const float* __restrict__ x2,
    float* __restrict__ out)
{
    const int row = blockIdx.x;
    const int tid = threadIdx.x;

    const float4* r1 = reinterpret_cast<const float4*>(x1 + (size_t)row * D_DIM);
    const float4* r2 = reinterpret_cast<const float4*>(x2 + (size_t)row * D_DIM);

    float dot = 0.f, sx = 0.f, sy = 0.f;

    // Single 16-deep load burst, then consume.
    float4 a[8], b[8];
#pragma unroll
    for (int i = 0; i < 8; ++i) a[i] = r1[tid + i * THREADS];
#pragma unroll
    for (int i = 0; i < 8; ++i) b[i] = r2[tid + i * THREADS];

#pragma unroll
    for (int i = 0; i < 8; ++i) {
        dot = fmaf(a[i].x, b[i].x, dot);
        dot = fmaf(a[i].y, b[i].y, dot);
        dot = fmaf(a[i].z, b[i].z, dot);
        dot = fmaf(a[i].w, b[i].w, dot);
        sx  = fmaf(a[i].x, a[i].x, sx);
        sx  = fmaf(a[i].y, a[i].y, sx);
        sx  = fmaf(a[i].z, a[i].z, sx);
        sx  = fmaf(a[i].w, a[i].w, sx);
        sy  = fmaf(b[i].x, b[i].x, sy);
        sy  = fmaf(b[i].y, b[i].y, sy);
        sy  = fmaf(b[i].z, b[i].z, sy);
        sy  = fmaf(b[i].w, b[i].w, sy);
    }

    // Warp reduce
#pragma unroll
    for (int off = 16; off > 0; off >>= 1) {
        dot += __shfl_down_sync(0xFFFFFFFFu, dot, off);
        sx  += __shfl_down_sync(0xFFFFFFFFu, sx,  off);
        sy  += __shfl_down_sync(0xFFFFFFFFu, sy,  off);
    }

    // Cross-warp (4 warps)
    __shared__ float s_dot[4], s_sx[4], s_sy[4];
    const int wid = tid >> 5;
    const int lid = tid & 31;
    if (lid == 0) { s_dot[wid] = dot; s_sx[wid] = sx; s_sy[wid] = sy; }
    __syncthreads();

    if (wid == 0) {
        dot = (lid < 4) ? s_dot[lid] : 0.f;
        sx  = (lid < 4) ? s_sx[lid]  : 0.f;
        sy  = (lid < 4) ? s_sy[lid]  : 0.f;
#pragma unroll
        for (int off = 2; off > 0; off >>= 1) {
            dot += __shfl_down_sync(0xFFFFFFFFu, dot, off);
            sx  += __shfl_down_sync(0xFFFFFFFFu, sx,  off);
            sy  += __shfl_down_sync(0xFFFFFFFFu, sy,  off);
        }
        if (lid == 0) {
            out[row] = 0.5f * dot * rsqrtf(sx * sy);
        }
    }
}

extern "C" void kernel_launch(void* const* d_in, const int* in_sizes, int n_in,
                              void* d_out, int out_size)
{
    const float* x1 = (const float*)d_in[0];
    const float* x2 = (const float*)d_in[1];
    float* out = (float*)d_out;
    const int B = out_size;  // 16384 rows
    cosine_rows_deep_kernel<<<B, THREADS>>>(x1, x2, out);
}